// round 3
// baseline (speedup 1.0000x reference)
#include <cuda_runtime.h>
#include <math.h>
#include <float.h>

#define BB 2
#define NN 4096
#define CC 64
#define BN (BB*NN)

// ---------------- device scratch (no allocations allowed) ----------------
__device__ float g_f1a[BN*CC];
__device__ float g_f2a[BN*CC];
__device__ float g_f2b[BN*CC];
__device__ float g_f1b[BN*CC];
__device__ float g_kn[2][BN*CC];     // normalized knn feats, point-major [b*N+n][c]
__device__ float4 g_xyz[2][BN];      // (x,y,z,|p|^2), [set][b*N+n]
__device__ int   g_idx[2*BN*16];     // [dir][b][n][16]: 0..7 cosine, 8..15 euclid

__device__ __forceinline__ float leaky(float x){ return fmaxf(x, 0.1f*x); }

#define INSERT8(dA, iA, dval, mval)                                         \
  if ((dval) < dA[7]) {                                                     \
    dA[7] = (dval); iA[7] = (mval);                                         \
    _Pragma("unroll")                                                       \
    for (int _i = 7; _i > 0; _i--) {                                        \
      if (dA[_i] < dA[_i-1]) {                                              \
        float _tv = dA[_i]; dA[_i] = dA[_i-1]; dA[_i-1] = _tv;              \
        int   _ti = iA[_i]; iA[_i] = iA[_i-1]; iA[_i-1] = _ti;              \
      }                                                                     \
    }                                                                       \
  }

// ---------------- 1x1 conv transforms: f1a,f2a,f2b,f1b -------------------
__global__ __launch_bounds__(256) void k_transform(
    const float* __restrict__ feat1, const float* __restrict__ feat2,
    const float* __restrict__ W11, const float* __restrict__ b11,
    const float* __restrict__ W22, const float* __restrict__ b22)
{
  int n0 = blockIdx.x * 64, b = blockIdx.y, combo = blockIdx.z;
  const float* src  = (combo == 0 || combo == 3) ? feat1 : feat2;
  const float* W    = (combo == 0 || combo == 2) ? W11 : W22;
  const float* bias = (combo == 0 || combo == 2) ? b11 : b22;
  float* dst = (combo == 0) ? g_f1a : (combo == 1) ? g_f2a : (combo == 2) ? g_f2b : g_f1b;

  __shared__ float sF[64*65];   // [c][nn]
  __shared__ float sWT[64*65];  // [c][d] = W[d][c]
  __shared__ float sB[64];
  int t = threadIdx.x;

  #pragma unroll
  for (int i = 0; i < 16; i++) {
    int idx = t + i*256;
    int hi = idx >> 6, lo = idx & 63;
    sF[hi*65 + lo]  = src[(b*64 + hi)*NN + n0 + lo];
    sWT[lo*65 + hi] = W[hi*64 + lo];
  }
  if (t < 64) sB[t] = bias[t];
  __syncthreads();

  int d = t & 63, g = t >> 6;
  for (int i = 0; i < 16; i++) {
    int nn = g*16 + i;
    float acc = sB[d];
    #pragma unroll
    for (int c = 0; c < 64; c++) acc += sWT[c*65 + d] * sF[c*65 + nn];
    dst[(b*NN + n0 + nn)*64 + d] = acc;
  }
}

// ---------------- normalize knn features (and transpose) ------------------
__global__ __launch_bounds__(256) void k_normalize(
    const float* __restrict__ knn1, const float* __restrict__ knn2)
{
  int n0 = blockIdx.x * 64, b = blockIdx.y, s = blockIdx.z;
  const float* src = s ? knn2 : knn1;
  __shared__ float sF[64*65];
  __shared__ float sInv[64];
  int t = threadIdx.x;

  #pragma unroll
  for (int i = 0; i < 16; i++) {
    int idx = t + i*256;
    int c = idx >> 6, x = idx & 63;
    sF[c*65 + x] = src[(b*64 + c)*NN + n0 + x];
  }
  __syncthreads();
  if (t < 64) {
    float sum = 0.f;
    #pragma unroll
    for (int c = 0; c < 64; c++) { float v = sF[c*65 + t]; sum += v*v; }
    sInv[t] = 1.0f / sqrtf(sum + 1e-8f);
  }
  __syncthreads();
  #pragma unroll
  for (int i = 0; i < 16; i++) {
    int idx = t + i*256;
    int c = idx & 63, x = idx >> 6;
    g_kn[s][(b*NN + n0 + x)*64 + c] = sF[c*65 + x] * sInv[x];
  }
}

// ---------------- xyz transpose + squared norms ---------------------------
__global__ __launch_bounds__(256) void k_xyz(
    const float* __restrict__ pc1, const float* __restrict__ pc2)
{
  int b = blockIdx.y, s = blockIdx.z;
  const float* pc = s ? pc2 : pc1;
  int n = blockIdx.x*256 + threadIdx.x;
  float x = pc[(b*3 + 0)*NN + n];
  float y = pc[(b*3 + 1)*NN + n];
  float z = pc[(b*3 + 2)*NN + n];
  g_xyz[s][b*NN + n] = make_float4(x, y, z, x*x + y*y + z*z);
}

// ---------------- dual KNN (cosine top-8 + euclid top-8) ------------------
__global__ __launch_bounds__(256) void k_knn()
{
  int dir = blockIdx.z, b = blockIdx.y;
  int qbase = blockIdx.x * 16;
  const float4* Qf = (const float4*)(dir ? g_kn[1] : g_kn[0]);
  const float4* Df = (const float4*)(dir ? g_kn[0] : g_kn[1]);
  const float4* Qx = dir ? g_xyz[1] : g_xyz[0];
  const float4* Dx = dir ? g_xyz[0] : g_xyz[1];

  int t = threadIdx.x, qi = t >> 4, sl = t & 15;
  int n = qbase + qi;

  float4 q4[16];
  #pragma unroll
  for (int c = 0; c < 16; c++) q4[c] = Qf[(b*NN + n)*16 + c];
  float4 qx = Qx[b*NN + n];

  float dC[8], dE[8]; int iC[8], iE[8];
  #pragma unroll
  for (int i = 0; i < 8; i++) { dC[i] = FLT_MAX; dE[i] = FLT_MAX; iC[i] = -1; iE[i] = -1; }

  __shared__ __align__(16) float sDF[32*68];
  __shared__ float4 sDX[32];
  __shared__ float mD[2048];
  __shared__ int   mI[2048];

  for (int mb = 0; mb < NN; mb += 32) {
    __syncthreads();
    #pragma unroll
    for (int i = 0; i < 2; i++) {
      int f = t + i*256;            // 512 float4s per tile
      int r = f >> 4, c4 = f & 15;
      *(float4*)&sDF[r*68 + c4*4] = Df[(b*NN + mb + r)*16 + c4];
    }
    if (t < 32) sDX[t] = Dx[b*NN + mb + t];
    __syncthreads();

    #pragma unroll
    for (int jj = 0; jj < 2; jj++) {
      int j = sl + jj*16;
      int m = mb + j;
      float4 acc = make_float4(0.f, 0.f, 0.f, 0.f);
      #pragma unroll
      for (int c = 0; c < 16; c++) {
        float4 v = *(const float4*)&sDF[j*68 + c*4];
        acc.x += q4[c].x * v.x; acc.y += q4[c].y * v.y;
        acc.z += q4[c].z * v.z; acc.w += q4[c].w * v.w;
      }
      float dot = (acc.x + acc.y) + (acc.z + acc.w);
      float dc = 1.0f - dot;
      INSERT8(dC, iC, dc, m);

      float4 dxv = sDX[j];
      float de = qx.w + dxv.w - 2.0f*(qx.x*dxv.x + qx.y*dxv.y + qx.z*dxv.z);
      INSERT8(dE, iE, de, m);
    }
  }

  int gbase = ((dir*BB + b)*NN + qbase)*16;  // + qi*16 per query below

  // merge cosine
  __syncthreads();
  #pragma unroll
  for (int i = 0; i < 8; i++) { mD[qi*128 + sl*8 + i] = dC[i]; mI[qi*128 + sl*8 + i] = iC[i]; }
  __syncthreads();
  if (t < 16) {
    int base = t*128;
    int gb = gbase + t*16;
    for (int r = 0; r < 8; r++) {
      float bd = FLT_MAX; int bs = 0;
      for (int s2 = 0; s2 < 128; s2++) { float v = mD[base + s2]; if (v < bd) { bd = v; bs = s2; } }
      g_idx[gb + r] = mI[base + bs];
      mD[base + bs] = FLT_MAX;
    }
  }
  __syncthreads();
  // merge euclid
  #pragma unroll
  for (int i = 0; i < 8; i++) { mD[qi*128 + sl*8 + i] = dE[i]; mI[qi*128 + sl*8 + i] = iE[i]; }
  __syncthreads();
  if (t < 16) {
    int base = t*128;
    int gb = gbase + t*16;
    for (int r = 0; r < 8; r++) {
      float bd = FLT_MAX; int bs = 0;
      for (int s2 = 0; s2 < 128; s2++) { float v = mD[base + s2]; if (v < bd) { bd = v; bs = s2; } }
      g_idx[gb + 8 + r] = mI[base + bs];
      mD[base + bs] = FLT_MAX;
    }
  }
}

// ---------------- gather + pos-MLP + 2x MLP + maxpool ---------------------
__global__ __launch_bounds__(128) void k_mlp(
    const float* __restrict__ Wpos, const float* __restrict__ bpos,
    const float* __restrict__ Wm1,  const float* __restrict__ b1,
    const float* __restrict__ Wm2,  const float* __restrict__ b2,
    float* __restrict__ out)
{
  int dir = blockIdx.z, b = blockIdx.y;
  int n0 = blockIdx.x * 2;  // 2 queries per block
  const float* p1 = dir ? g_f2b : g_f1a;
  const float* p2 = dir ? g_f1b : g_f2a;
  const float4* Qx = dir ? g_xyz[1] : g_xyz[0];
  const float4* Dx = dir ? g_xyz[0] : g_xyz[1];

  __shared__ __align__(16) float sW[64*68];
  __shared__ __align__(16) float bufA[2*16*68];
  __shared__ __align__(16) float bufB[2*16*68];
  __shared__ float sP1[2*64];
  __shared__ float4 sPos[64];
  __shared__ float sB1[64], sB2[64];
  __shared__ float4 sDir[32];
  __shared__ int sNb[32];

  int t = threadIdx.x;

  #pragma unroll
  for (int i = 0; i < 32; i++) {
    int idx = t + i*128;
    int e = idx >> 6, d = idx & 63;
    sW[e*68 + d] = Wm1[idx];
  }
  if (t < 64) {
    sPos[t] = make_float4(Wpos[t*3], Wpos[t*3+1], Wpos[t*3+2], bpos[t]);
    sB1[t] = b1[t];
    sB2[t] = b2[t];
  }
  { int q = t >> 6, d = t & 63; sP1[t] = p1[(b*NN + n0 + q)*64 + d]; }
  if (t < 32) {
    int q = t >> 4, k = t & 15;
    int nb = g_idx[((dir*BB + b)*NN + n0 + q)*16 + k];
    sNb[t] = nb;
    float4 dxv = Dx[b*NN + nb], qxv = Qx[b*NN + n0 + q];
    sDir[t] = make_float4(dxv.x - qxv.x, dxv.y - qxv.y, dxv.z - qxv.z, 0.f);
  }
  __syncthreads();

  // stage 0: leaky(g2 + p1 + pos)
  #pragma unroll
  for (int i = 0; i < 16; i++) {
    int elem = t + i*128;
    int d = elem & 63, k = (elem >> 6) & 15, q = elem >> 10;
    int nb = sNb[q*16 + k];
    float4 dv = sDir[q*16 + k];
    float4 wp = sPos[d];
    float pos = dv.x*wp.x + dv.y*wp.y + dv.z*wp.z + wp.w;
    float v = p2[(b*NN + nb)*64 + d] + sP1[q*64 + d] + pos;
    bufA[(q*16 + k)*68 + d] = leaky(v);
  }
  __syncthreads();

  // stage 1: bufA @ Wm1^T -> bufB
  #pragma unroll
  for (int i = 0; i < 16; i++) {
    int elem = t + i*128;
    int k = elem & 15, e = (elem >> 4) & 63, q = elem >> 10;
    int ro = (q*16 + k)*68;
    float4 acc = make_float4(0.f, 0.f, 0.f, 0.f);
    #pragma unroll
    for (int c = 0; c < 16; c++) {
      float4 a = *(const float4*)&bufA[ro + c*4];
      float4 w = *(const float4*)&sW[e*68 + c*4];
      acc.x += a.x*w.x; acc.y += a.y*w.y; acc.z += a.z*w.z; acc.w += a.w*w.w;
    }
    bufB[ro + e] = leaky(sB1[e] + (acc.x + acc.y) + (acc.z + acc.w));
  }
  __syncthreads();

  // swap weights to Wm2
  #pragma unroll
  for (int i = 0; i < 32; i++) {
    int idx = t + i*128;
    int e = idx >> 6, d = idx & 63;
    sW[e*68 + d] = Wm2[idx];
  }
  __syncthreads();

  // stage 2: bufB @ Wm2^T -> bufA
  #pragma unroll
  for (int i = 0; i < 16; i++) {
    int elem = t + i*128;
    int k = elem & 15, e = (elem >> 4) & 63, q = elem >> 10;
    int ro = (q*16 + k)*68;
    float4 acc = make_float4(0.f, 0.f, 0.f, 0.f);
    #pragma unroll
    for (int c = 0; c < 16; c++) {
      float4 a = *(const float4*)&bufB[ro + c*4];
      float4 w = *(const float4*)&sW[e*68 + c*4];
      acc.x += a.x*w.x; acc.y += a.y*w.y; acc.z += a.z*w.z; acc.w += a.w*w.w;
    }
    bufA[ro + e] = leaky(sB2[e] + (acc.x + acc.y) + (acc.z + acc.w));
  }
  __syncthreads();

  // maxpool over neighbors + store [dir][b][e][n]
  {
    int q = t >> 6, e = t & 63;
    float m = -FLT_MAX;
    #pragma unroll
    for (int k = 0; k < 16; k++) m = fmaxf(m, bufA[(q*16 + k)*68 + e]);
    out[dir*(BB*64*NN) + b*(64*NN) + e*NN + (n0 + q)] = m;
  }
}

// ---------------- launch ---------------------------------------------------
extern "C" void kernel_launch(void* const* d_in, const int* in_sizes, int n_in,
                              void* d_out, int out_size)
{
  const float* pc1   = (const float*)d_in[0];
  const float* pc2   = (const float*)d_in[1];
  const float* feat1 = (const float*)d_in[2];
  const float* feat2 = (const float*)d_in[3];
  const float* knn1  = (const float*)d_in[4];
  const float* knn2  = (const float*)d_in[5];
  const float* W11   = (const float*)d_in[6];
  const float* b11   = (const float*)d_in[7];
  const float* W22   = (const float*)d_in[8];
  const float* b22   = (const float*)d_in[9];
  const float* Wpos  = (const float*)d_in[10];
  const float* bpos  = (const float*)d_in[11];
  const float* Wm1   = (const float*)d_in[12];
  const float* bm1   = (const float*)d_in[13];
  const float* Wm2   = (const float*)d_in[14];
  const float* bm2   = (const float*)d_in[15];
  float* out = (float*)d_out;

  k_transform<<<dim3(64, 2, 4), 256>>>(feat1, feat2, W11, b11, W22, b22);
  k_normalize<<<dim3(64, 2, 2), 256>>>(knn1, knn2);
  k_xyz<<<dim3(16, 2, 2), 256>>>(pc1, pc2);
  k_knn<<<dim3(256, 2, 2), 256>>>();
  k_mlp<<<dim3(2048, 2, 2), 128>>>(Wpos, bpos, Wm1, bm1, Wm2, bm2, out);
}

// round 4
// speedup vs baseline: 1.3610x; 1.3610x over previous
#include <cuda_runtime.h>
#include <math.h>
#include <float.h>

#define BB 2
#define NN 4096
#define CC 64
#define BN (BB*NN)

// ---------------- device scratch (no allocations allowed) ----------------
__device__ float g_f1a[BN*CC];       // point-major [b*N+n][d]
__device__ float g_f2a[BN*CC];
__device__ float g_f2b[BN*CC];
__device__ float g_f1b[BN*CC];
__device__ float g_kn[2][CC*BN];     // channel-major [s][(b*64+c)*NN + n]
__device__ float4 g_xyz[2][BN];      // (x,y,z,|p|^2)
__device__ int   g_idx[2*BN*16];     // [dir][b][n][16]: 0..7 cosine, 8..15 euclid

__device__ __forceinline__ float leaky(float x){ return fmaxf(x, 0.1f*x); }

#define INSERT8(dA, iA, dval, mval)                                         \
  if ((dval) < dA[7]) {                                                     \
    dA[7] = (dval); iA[7] = (mval);                                         \
    _Pragma("unroll")                                                       \
    for (int _i = 7; _i > 0; _i--) {                                        \
      if (dA[_i] < dA[_i-1]) {                                              \
        float _tv = dA[_i]; dA[_i] = dA[_i-1]; dA[_i-1] = _tv;              \
        int   _ti = iA[_i]; iA[_i] = iA[_i-1]; iA[_i-1] = _ti;              \
      }                                                                     \
    }                                                                       \
  }

// ---------------- 1x1 conv transforms: f1a,f2a,f2b,f1b -------------------
__global__ __launch_bounds__(256) void k_transform(
    const float* __restrict__ feat1, const float* __restrict__ feat2,
    const float* __restrict__ W11, const float* __restrict__ b11,
    const float* __restrict__ W22, const float* __restrict__ b22)
{
  int n0 = blockIdx.x * 64, b = blockIdx.y, combo = blockIdx.z;
  const float* src  = (combo == 0 || combo == 3) ? feat1 : feat2;
  const float* W    = (combo == 0 || combo == 2) ? W11 : W22;
  const float* bias = (combo == 0 || combo == 2) ? b11 : b22;
  float* dst = (combo == 0) ? g_f1a : (combo == 1) ? g_f2a : (combo == 2) ? g_f2b : g_f1b;

  __shared__ float sF[64*65];   // [c][nn]
  __shared__ float sWT[64*65];  // [c][d]
  __shared__ float sB[64];
  int t = threadIdx.x;

  #pragma unroll
  for (int i = 0; i < 16; i++) {
    int idx = t + i*256;
    int hi = idx >> 6, lo = idx & 63;
    sF[hi*65 + lo]  = src[(b*64 + hi)*NN + n0 + lo];
    sWT[lo*65 + hi] = W[hi*64 + lo];
  }
  if (t < 64) sB[t] = bias[t];
  __syncthreads();

  int d = t & 63, g = t >> 6;
  for (int i = 0; i < 16; i++) {
    int nn = g*16 + i;
    float acc = sB[d];
    #pragma unroll
    for (int c = 0; c < 64; c++) acc += sWT[c*65 + d] * sF[c*65 + nn];
    dst[(b*NN + n0 + nn)*64 + d] = acc;
  }
}

// ------- normalize knn features (stay channel-major, just scale) ----------
__global__ __launch_bounds__(256) void k_normalize(
    const float* __restrict__ knn1, const float* __restrict__ knn2)
{
  int n0 = blockIdx.x * 64, b = blockIdx.y, s = blockIdx.z;
  const float* src = s ? knn2 : knn1;
  __shared__ float sF[64*65];
  __shared__ float sInv[64];
  int t = threadIdx.x;

  #pragma unroll
  for (int i = 0; i < 16; i++) {
    int idx = t + i*256;
    int c = idx >> 6, x = idx & 63;
    sF[c*65 + x] = src[(b*64 + c)*NN + n0 + x];
  }
  __syncthreads();
  if (t < 64) {
    float sum = 0.f;
    #pragma unroll
    for (int c = 0; c < 64; c++) { float v = sF[c*65 + t]; sum += v*v; }
    sInv[t] = 1.0f / sqrtf(sum + 1e-8f);
  }
  __syncthreads();
  #pragma unroll
  for (int i = 0; i < 16; i++) {
    int idx = t + i*256;
    int c = idx >> 6, x = idx & 63;
    g_kn[s][(b*64 + c)*NN + n0 + x] = sF[c*65 + x] * sInv[x];
  }
}

// ---------------- xyz transpose + squared norms ---------------------------
__global__ __launch_bounds__(256) void k_xyz(
    const float* __restrict__ pc1, const float* __restrict__ pc2)
{
  int b = blockIdx.y, s = blockIdx.z;
  const float* pc = s ? pc2 : pc1;
  int n = blockIdx.x*256 + threadIdx.x;
  float x = pc[(b*3 + 0)*NN + n];
  float y = pc[(b*3 + 1)*NN + n];
  float z = pc[(b*3 + 2)*NN + n];
  g_xyz[s][b*NN + n] = make_float4(x, y, z, x*x + y*y + z*z);
}

// --------- cosine KNN: tiled outer-product GEMM + top-8 scan --------------
// block = 256 thr; 64 queries/block; candidate tiles of 64.
// smem (dynamic 52224B): sQ[64c][68], sD[64c][68], dist[64q][68] (+merge union)
__global__ __launch_bounds__(256) void k_knn_cos()
{
  extern __shared__ float smem[];
  float* sQ   = smem;             // 4352 floats
  float* sD   = smem + 4352;      // 4352 floats
  float* dist = smem + 8704;      // 4352 floats

  int dir = blockIdx.z, b = blockIdx.y;
  int qbase = blockIdx.x * 64;
  const float* Qg = dir ? g_kn[1] : g_kn[0];
  const float* Dg = dir ? g_kn[0] : g_kn[1];

  int t = threadIdx.x;
  int tq = t >> 4, tm = t & 15;   // GEMM tile coords
  int sq = t >> 2, sl = t & 3;    // scan coords: 4 threads per query

  // fill sQ [c][q]  (channel-major gmem: contiguous in q)
  {
    int c0 = t >> 4, m4 = t & 15;
    #pragma unroll
    for (int i = 0; i < 4; i++) {
      int c = c0 + 16*i;
      *(float4*)&sQ[c*68 + m4*4] =
        *(const float4*)&Qg[(b*64 + c)*NN + qbase + m4*4];
    }
  }

  float dC[8]; int iC[8];
  #pragma unroll
  for (int i = 0; i < 8; i++) { dC[i] = FLT_MAX; iC[i] = -1; }

  for (int mb = 0; mb < NN; mb += 64) {
    __syncthreads();   // protect sD/dist from previous tile
    {
      int c0 = t >> 4, m4 = t & 15;
      #pragma unroll
      for (int i = 0; i < 4; i++) {
        int c = c0 + 16*i;
        *(float4*)&sD[c*68 + m4*4] =
          *(const float4*)&Dg[(b*64 + c)*NN + mb + m4*4];
      }
    }
    __syncthreads();

    // outer-product GEMM: 4q x 4m per thread
    float a00=0,a01=0,a02=0,a03=0, a10=0,a11=0,a12=0,a13=0;
    float a20=0,a21=0,a22=0,a23=0, a30=0,a31=0,a32=0,a33=0;
    #pragma unroll 8
    for (int c = 0; c < 64; c++) {
      float4 qf = *(const float4*)&sQ[c*68 + tq*4];
      float4 mf = *(const float4*)&sD[c*68 + tm*4];
      a00 += qf.x*mf.x; a01 += qf.x*mf.y; a02 += qf.x*mf.z; a03 += qf.x*mf.w;
      a10 += qf.y*mf.x; a11 += qf.y*mf.y; a12 += qf.y*mf.z; a13 += qf.y*mf.w;
      a20 += qf.z*mf.x; a21 += qf.z*mf.y; a22 += qf.z*mf.z; a23 += qf.z*mf.w;
      a30 += qf.w*mf.x; a31 += qf.w*mf.y; a32 += qf.w*mf.z; a33 += qf.w*mf.w;
    }
    // write distances (1 - dot)
    *(float4*)&dist[(tq*4+0)*68 + tm*4] = make_float4(1.f-a00, 1.f-a01, 1.f-a02, 1.f-a03);
    *(float4*)&dist[(tq*4+1)*68 + tm*4] = make_float4(1.f-a10, 1.f-a11, 1.f-a12, 1.f-a13);
    *(float4*)&dist[(tq*4+2)*68 + tm*4] = make_float4(1.f-a20, 1.f-a21, 1.f-a22, 1.f-a23);
    *(float4*)&dist[(tq*4+3)*68 + tm*4] = make_float4(1.f-a30, 1.f-a31, 1.f-a32, 1.f-a33);
    __syncthreads();

    // scan: thread (sq, sl) handles candidates sl*16 .. sl*16+15 (index order)
    #pragma unroll
    for (int i4 = 0; i4 < 4; i4++) {
      float4 dv = *(const float4*)&dist[sq*68 + sl*16 + i4*4];
      int m0 = mb + sl*16 + i4*4;
      INSERT8(dC, iC, dv.x, m0+0);
      INSERT8(dC, iC, dv.y, m0+1);
      INSERT8(dC, iC, dv.z, m0+2);
      INSERT8(dC, iC, dv.w, m0+3);
    }
  }

  // final merge: 4 sorted runs of 8 per query -> top-8
  __syncthreads();
  float* mD = dist;                 // reuse dist area: 2048 floats
  int*   mI = (int*)(dist + 2048);  // + 2048 ints (fits in 4352 floats)
  #pragma unroll
  for (int i = 0; i < 8; i++) {
    mD[(sq*4 + sl)*8 + i] = dC[i];
    mI[(sq*4 + sl)*8 + i] = iC[i];
  }
  __syncthreads();
  if (t < 64) {
    int base = t*32;
    int gb = ((dir*BB + b)*NN + qbase + t)*16;
    for (int r = 0; r < 8; r++) {
      float bd = FLT_MAX; int bs = 0;
      #pragma unroll
      for (int s2 = 0; s2 < 32; s2++) {
        float v = mD[base + s2];
        if (v < bd) { bd = v; bs = s2; }
      }
      g_idx[gb + r] = mI[base + bs];
      mD[base + bs] = FLT_MAX;
    }
  }
}

// --------- euclid KNN: 1 thread per query, broadcast candidate tiles ------
__global__ __launch_bounds__(256) void k_euclid()
{
  int dir = blockIdx.z, b = blockIdx.y;
  int q = blockIdx.x*256 + threadIdx.x;
  const float4* Qx = dir ? g_xyz[1] : g_xyz[0];
  const float4* Dx = dir ? g_xyz[0] : g_xyz[1];
  int t = threadIdx.x;

  float4 qx = Qx[b*NN + q];
  float dE[8]; int iE[8];
  #pragma unroll
  for (int i = 0; i < 8; i++) { dE[i] = FLT_MAX; iE[i] = -1; }

  __shared__ float4 sT[128];
  for (int mb = 0; mb < NN; mb += 128) {
    __syncthreads();
    if (t < 128) sT[t] = Dx[b*NN + mb + t];
    __syncthreads();
    #pragma unroll 4
    for (int j = 0; j < 128; j++) {
      float4 d = sT[j];
      float de = qx.w + d.w - 2.0f*(qx.x*d.x + qx.y*d.y + qx.z*d.z);
      INSERT8(dE, iE, de, mb + j);
    }
  }
  int gb = ((dir*BB + b)*NN + q)*16;
  #pragma unroll
  for (int i = 0; i < 8; i++) g_idx[gb + 8 + i] = iE[i];
}

// ---------------- gather + pos-MLP + 2x MLP + maxpool ---------------------
__global__ __launch_bounds__(128) void k_mlp(
    const float* __restrict__ Wpos, const float* __restrict__ bpos,
    const float* __restrict__ Wm1,  const float* __restrict__ b1,
    const float* __restrict__ Wm2,  const float* __restrict__ b2,
    float* __restrict__ out)
{
  int dir = blockIdx.z, b = blockIdx.y;
  int n0 = blockIdx.x * 2;
  const float* p1 = dir ? g_f2b : g_f1a;
  const float* p2 = dir ? g_f1b : g_f2a;
  const float4* Qx = dir ? g_xyz[1] : g_xyz[0];
  const float4* Dx = dir ? g_xyz[0] : g_xyz[1];

  __shared__ __align__(16) float sW[64*68];
  __shared__ __align__(16) float bufA[2*16*68];
  __shared__ __align__(16) float bufB[2*16*68];
  __shared__ float sP1[2*64];
  __shared__ float4 sPos[64];
  __shared__ float sB1[64], sB2[64];
  __shared__ float4 sDir[32];
  __shared__ int sNb[32];

  int t = threadIdx.x;

  #pragma unroll
  for (int i = 0; i < 32; i++) {
    int idx = t + i*128;
    int e = idx >> 6, d = idx & 63;
    sW[e*68 + d] = Wm1[idx];
  }
  if (t < 64) {
    sPos[t] = make_float4(Wpos[t*3], Wpos[t*3+1], Wpos[t*3+2], bpos[t]);
    sB1[t] = b1[t];
    sB2[t] = b2[t];
  }
  { int q = t >> 6, d = t & 63; sP1[t] = p1[(b*NN + n0 + q)*64 + d]; }
  if (t < 32) {
    int q = t >> 4, k = t & 15;
    int nb = g_idx[((dir*BB + b)*NN + n0 + q)*16 + k];
    sNb[t] = nb;
    float4 dxv = Dx[b*NN + nb], qxv = Qx[b*NN + n0 + q];
    sDir[t] = make_float4(dxv.x - qxv.x, dxv.y - qxv.y, dxv.z - qxv.z, 0.f);
  }
  __syncthreads();

  #pragma unroll
  for (int i = 0; i < 16; i++) {
    int elem = t + i*128;
    int d = elem & 63, k = (elem >> 6) & 15, q = elem >> 10;
    int nb = sNb[q*16 + k];
    float4 dv = sDir[q*16 + k];
    float4 wp = sPos[d];
    float pos = dv.x*wp.x + dv.y*wp.y + dv.z*wp.z + wp.w;
    float v = p2[(b*NN + nb)*64 + d] + sP1[q*64 + d] + pos;
    bufA[(q*16 + k)*68 + d] = leaky(v);
  }
  __syncthreads();

  #pragma unroll
  for (int i = 0; i < 16; i++) {
    int elem = t + i*128;
    int k = elem & 15, e = (elem >> 4) & 63, q = elem >> 10;
    int ro = (q*16 + k)*68;
    float4 acc = make_float4(0.f, 0.f, 0.f, 0.f);
    #pragma unroll
    for (int c = 0; c < 16; c++) {
      float4 a = *(const float4*)&bufA[ro + c*4];
      float4 w = *(const float4*)&sW[e*68 + c*4];
      acc.x += a.x*w.x; acc.y += a.y*w.y; acc.z += a.z*w.z; acc.w += a.w*w.w;
    }
    bufB[ro + e] = leaky(sB1[e] + (acc.x + acc.y) + (acc.z + acc.w));
  }
  __syncthreads();

  #pragma unroll
  for (int i = 0; i < 32; i++) {
    int idx = t + i*128;
    int e = idx >> 6, d = idx & 63;
    sW[e*68 + d] = Wm2[idx];
  }
  __syncthreads();

  #pragma unroll
  for (int i = 0; i < 16; i++) {
    int elem = t + i*128;
    int k = elem & 15, e = (elem >> 4) & 63, q = elem >> 10;
    int ro = (q*16 + k)*68;
    float4 acc = make_float4(0.f, 0.f, 0.f, 0.f);
    #pragma unroll
    for (int c = 0; c < 16; c++) {
      float4 a = *(const float4*)&bufB[ro + c*4];
      float4 w = *(const float4*)&sW[e*68 + c*4];
      acc.x += a.x*w.x; acc.y += a.y*w.y; acc.z += a.z*w.z; acc.w += a.w*w.w;
    }
    bufA[ro + e] = leaky(sB2[e] + (acc.x + acc.y) + (acc.z + acc.w));
  }
  __syncthreads();

  {
    int q = t >> 6, e = t & 63;
    float m = -FLT_MAX;
    #pragma unroll
    for (int k = 0; k < 16; k++) m = fmaxf(m, bufA[(q*16 + k)*68 + e]);
    out[dir*(BB*64*NN) + b*(64*NN) + e*NN + (n0 + q)] = m;
  }
}

// ---------------- launch ---------------------------------------------------
extern "C" void kernel_launch(void* const* d_in, const int* in_sizes, int n_in,
                              void* d_out, int out_size)
{
  const float* pc1   = (const float*)d_in[0];
  const float* pc2   = (const float*)d_in[1];
  const float* feat1 = (const float*)d_in[2];
  const float* feat2 = (const float*)d_in[3];
  const float* knn1  = (const float*)d_in[4];
  const float* knn2  = (const float*)d_in[5];
  const float* W11   = (const float*)d_in[6];
  const float* b11   = (const float*)d_in[7];
  const float* W22   = (const float*)d_in[8];
  const float* b22   = (const float*)d_in[9];
  const float* Wpos  = (const float*)d_in[10];
  const float* bpos  = (const float*)d_in[11];
  const float* Wm1   = (const float*)d_in[12];
  const float* bm1   = (const float*)d_in[13];
  const float* Wm2   = (const float*)d_in[14];
  const float* bm2   = (const float*)d_in[15];
  float* out = (float*)d_out;

  cudaFuncSetAttribute(k_knn_cos, cudaFuncAttributeMaxDynamicSharedMemorySize, 52224);

  k_transform<<<dim3(64, 2, 4), 256>>>(feat1, feat2, W11, b11, W22, b22);
  k_normalize<<<dim3(64, 2, 2), 256>>>(knn1, knn2);
  k_xyz<<<dim3(16, 2, 2), 256>>>(pc1, pc2);
  k_knn_cos<<<dim3(64, 2, 2), 256, 52224>>>();
  k_euclid<<<dim3(16, 2, 2), 256>>>();
  k_mlp<<<dim3(2048, 2, 2), 128>>>(Wpos, bpos, Wm1, bm1, Wm2, bm2, out);
}

// round 5
// speedup vs baseline: 1.9710x; 1.4482x over previous
#include <cuda_runtime.h>
#include <math.h>
#include <float.h>

#define BB 2
#define NN 4096
#define CC 64
#define BN (BB*NN)

// ---------------- device scratch (no allocations allowed) ----------------
__device__ float g_f1a[BN*CC];       // point-major [b*N+n][d]
__device__ float g_f2a[BN*CC];
__device__ float g_f2b[BN*CC];
__device__ float g_f1b[BN*CC];
__device__ float g_kn[2][CC*BN];     // channel-major [s][(b*64+c)*NN + n]
__device__ float4 g_xyz[2][BN];      // (x,y,z,|p|^2)
__device__ int   g_idx[2*BN*16];     // [dir][b][n][16]: 0..7 cosine, 8..15 euclid

__device__ __forceinline__ float leaky(float x){ return fmaxf(x, 0.1f*x); }

#define INSERT8(dA, iA, dval, mval)                                         \
  if ((dval) < dA[7]) {                                                     \
    dA[7] = (dval); iA[7] = (mval);                                         \
    _Pragma("unroll")                                                       \
    for (int _i = 7; _i > 0; _i--) {                                        \
      if (dA[_i] < dA[_i-1]) {                                              \
        float _tv = dA[_i]; dA[_i] = dA[_i-1]; dA[_i-1] = _tv;              \
        int   _ti = iA[_i]; iA[_i] = iA[_i-1]; iA[_i-1] = _ti;              \
      }                                                                     \
    }                                                                       \
  }

// ---------------- 1x1 conv transforms: f1a,f2a,f2b,f1b -------------------
__global__ __launch_bounds__(256) void k_transform(
    const float* __restrict__ feat1, const float* __restrict__ feat2,
    const float* __restrict__ W11, const float* __restrict__ b11,
    const float* __restrict__ W22, const float* __restrict__ b22)
{
  int n0 = blockIdx.x * 64, b = blockIdx.y, combo = blockIdx.z;
  const float* src  = (combo == 0 || combo == 3) ? feat1 : feat2;
  const float* W    = (combo == 0 || combo == 2) ? W11 : W22;
  const float* bias = (combo == 0 || combo == 2) ? b11 : b22;
  float* dst = (combo == 0) ? g_f1a : (combo == 1) ? g_f2a : (combo == 2) ? g_f2b : g_f1b;

  __shared__ float sF[64*65];   // [c][nn]
  __shared__ float sWT[64*65];  // [c][d]
  __shared__ float sB[64];
  int t = threadIdx.x;

  #pragma unroll
  for (int i = 0; i < 16; i++) {
    int idx = t + i*256;
    int hi = idx >> 6, lo = idx & 63;
    sF[hi*65 + lo]  = src[(b*64 + hi)*NN + n0 + lo];
    sWT[lo*65 + hi] = W[hi*64 + lo];
  }
  if (t < 64) sB[t] = bias[t];
  __syncthreads();

  int d = t & 63, g = t >> 6;
  for (int i = 0; i < 16; i++) {
    int nn = g*16 + i;
    float acc = sB[d];
    #pragma unroll
    for (int c = 0; c < 64; c++) acc += sWT[c*65 + d] * sF[c*65 + nn];
    dst[(b*NN + n0 + nn)*64 + d] = acc;
  }
}

// ------- normalize knn features (stay channel-major, just scale) ----------
__global__ __launch_bounds__(256) void k_normalize(
    const float* __restrict__ knn1, const float* __restrict__ knn2)
{
  int n0 = blockIdx.x * 64, b = blockIdx.y, s = blockIdx.z;
  const float* src = s ? knn2 : knn1;
  __shared__ float sF[64*65];
  __shared__ float sInv[64];
  int t = threadIdx.x;

  #pragma unroll
  for (int i = 0; i < 16; i++) {
    int idx = t + i*256;
    int c = idx >> 6, x = idx & 63;
    sF[c*65 + x] = src[(b*64 + c)*NN + n0 + x];
  }
  __syncthreads();
  if (t < 64) {
    float sum = 0.f;
    #pragma unroll
    for (int c = 0; c < 64; c++) { float v = sF[c*65 + t]; sum += v*v; }
    sInv[t] = 1.0f / sqrtf(sum + 1e-8f);
  }
  __syncthreads();
  #pragma unroll
  for (int i = 0; i < 16; i++) {
    int idx = t + i*256;
    int c = idx >> 6, x = idx & 63;
    g_kn[s][(b*64 + c)*NN + n0 + x] = sF[c*65 + x] * sInv[x];
  }
}

// ---------------- xyz transpose + squared norms ---------------------------
__global__ __launch_bounds__(256) void k_xyz(
    const float* __restrict__ pc1, const float* __restrict__ pc2)
{
  int b = blockIdx.y, s = blockIdx.z;
  const float* pc = s ? pc2 : pc1;
  int n = blockIdx.x*256 + threadIdx.x;
  float x = pc[(b*3 + 0)*NN + n];
  float y = pc[(b*3 + 1)*NN + n];
  float z = pc[(b*3 + 2)*NN + n];
  g_xyz[s][b*NN + n] = make_float4(x, y, z, x*x + y*y + z*z);
}

// --------- cosine KNN: tiled outer-product GEMM + top-8 scan --------------
__global__ __launch_bounds__(256) void k_knn_cos()
{
  extern __shared__ float smem[];
  float* sQ   = smem;             // 4352 floats
  float* sD   = smem + 4352;      // 4352 floats
  float* dist = smem + 8704;      // 4352 floats

  int dir = blockIdx.z, b = blockIdx.y;
  int qbase = blockIdx.x * 64;
  const float* Qg = dir ? g_kn[1] : g_kn[0];
  const float* Dg = dir ? g_kn[0] : g_kn[1];

  int t = threadIdx.x;
  int tq = t >> 4, tm = t & 15;
  int sq = t >> 2, sl = t & 3;

  {
    int c0 = t >> 4, m4 = t & 15;
    #pragma unroll
    for (int i = 0; i < 4; i++) {
      int c = c0 + 16*i;
      *(float4*)&sQ[c*68 + m4*4] =
        *(const float4*)&Qg[(b*64 + c)*NN + qbase + m4*4];
    }
  }

  float dC[8]; int iC[8];
  #pragma unroll
  for (int i = 0; i < 8; i++) { dC[i] = FLT_MAX; iC[i] = -1; }

  for (int mb = 0; mb < NN; mb += 64) {
    __syncthreads();
    {
      int c0 = t >> 4, m4 = t & 15;
      #pragma unroll
      for (int i = 0; i < 4; i++) {
        int c = c0 + 16*i;
        *(float4*)&sD[c*68 + m4*4] =
          *(const float4*)&Dg[(b*64 + c)*NN + mb + m4*4];
      }
    }
    __syncthreads();

    float a00=0,a01=0,a02=0,a03=0, a10=0,a11=0,a12=0,a13=0;
    float a20=0,a21=0,a22=0,a23=0, a30=0,a31=0,a32=0,a33=0;
    #pragma unroll 8
    for (int c = 0; c < 64; c++) {
      float4 qf = *(const float4*)&sQ[c*68 + tq*4];
      float4 mf = *(const float4*)&sD[c*68 + tm*4];
      a00 += qf.x*mf.x; a01 += qf.x*mf.y; a02 += qf.x*mf.z; a03 += qf.x*mf.w;
      a10 += qf.y*mf.x; a11 += qf.y*mf.y; a12 += qf.y*mf.z; a13 += qf.y*mf.w;
      a20 += qf.z*mf.x; a21 += qf.z*mf.y; a22 += qf.z*mf.z; a23 += qf.z*mf.w;
      a30 += qf.w*mf.x; a31 += qf.w*mf.y; a32 += qf.w*mf.z; a33 += qf.w*mf.w;
    }
    *(float4*)&dist[(tq*4+0)*68 + tm*4] = make_float4(1.f-a00, 1.f-a01, 1.f-a02, 1.f-a03);
    *(float4*)&dist[(tq*4+1)*68 + tm*4] = make_float4(1.f-a10, 1.f-a11, 1.f-a12, 1.f-a13);
    *(float4*)&dist[(tq*4+2)*68 + tm*4] = make_float4(1.f-a20, 1.f-a21, 1.f-a22, 1.f-a23);
    *(float4*)&dist[(tq*4+3)*68 + tm*4] = make_float4(1.f-a30, 1.f-a31, 1.f-a32, 1.f-a33);
    __syncthreads();

    #pragma unroll
    for (int i4 = 0; i4 < 4; i4++) {
      float4 dv = *(const float4*)&dist[sq*68 + sl*16 + i4*4];
      int m0 = mb + sl*16 + i4*4;
      INSERT8(dC, iC, dv.x, m0+0);
      INSERT8(dC, iC, dv.y, m0+1);
      INSERT8(dC, iC, dv.z, m0+2);
      INSERT8(dC, iC, dv.w, m0+3);
    }
  }

  __syncthreads();
  float* mD = dist;
  int*   mI = (int*)(dist + 2048);
  #pragma unroll
  for (int i = 0; i < 8; i++) {
    mD[(sq*4 + sl)*8 + i] = dC[i];
    mI[(sq*4 + sl)*8 + i] = iC[i];
  }
  __syncthreads();
  if (t < 64) {
    int base = t*32;
    int gb = ((dir*BB + b)*NN + qbase + t)*16;
    for (int r = 0; r < 8; r++) {
      float bd = FLT_MAX; int bs = 0;
      #pragma unroll
      for (int s2 = 0; s2 < 32; s2++) {
        float v = mD[base + s2];
        if (v < bd) { bd = v; bs = s2; }
      }
      g_idx[gb + r] = mI[base + bs];
      mD[base + bs] = FLT_MAX;
    }
  }
}

// --------- euclid KNN: 4 threads/query, blocked ranges, smem merge --------
__global__ __launch_bounds__(256) void k_euclid()
{
  int dir = blockIdx.z, b = blockIdx.y;
  int qbase = blockIdx.x * 64;
  const float4* Qx = dir ? g_xyz[1] : g_xyz[0];
  const float4* Dx = dir ? g_xyz[0] : g_xyz[1];
  int t = threadIdx.x;
  int ql = t >> 2, sl = t & 3;       // 4 threads per query, blocked quarters
  int q = qbase + ql;

  float4 qx = Qx[b*NN + q];
  float dE[8]; int iE[8];
  #pragma unroll
  for (int i = 0; i < 8; i++) { dE[i] = FLT_MAX; iE[i] = -1; }

  const float4* base = &Dx[b*NN + sl*1024];
  #pragma unroll 4
  for (int i = 0; i < 1024; i++) {
    float4 d = __ldg(&base[i]);
    float de = qx.w + d.w - 2.0f*(qx.x*d.x + qx.y*d.y + qx.z*d.z);
    INSERT8(dE, iE, de, sl*1024 + i);
  }

  __shared__ float mD[2048];
  __shared__ int   mI[2048];
  #pragma unroll
  for (int i = 0; i < 8; i++) { mD[t*8 + i] = dE[i]; mI[t*8 + i] = iE[i]; }
  __syncthreads();
  if (t < 64) {
    int mb = t*32;
    int gb = ((dir*BB + b)*NN + qbase + t)*16 + 8;
    for (int r = 0; r < 8; r++) {
      float bd = FLT_MAX; int bs = 0;
      #pragma unroll
      for (int s2 = 0; s2 < 32; s2++) {
        float v = mD[mb + s2];
        if (v < bd) { bd = v; bs = s2; }
      }
      g_idx[gb + r] = mI[mb + bs];
      mD[mb + bs] = FLT_MAX;
    }
  }
}

// ------ gather + pos-MLP + 2x MLP (register-blocked GEMM) + maxpool -------
// 8 queries/block -> 128 rows. Buffers column-major [c][row], row stride 136.
// smem layout (floats): sW 4352 | bufA 8704 | bufB 8704 | sP1 512 | sPos 256
//                       | sB1 64 | sB2 64 | sDir 512 | sNb 128  = 23296 (93184B)
__global__ __launch_bounds__(256) void k_mlp(
    const float* __restrict__ Wpos, const float* __restrict__ bpos,
    const float* __restrict__ Wm1,  const float* __restrict__ b1,
    const float* __restrict__ Wm2,  const float* __restrict__ b2,
    float* __restrict__ out)
{
  extern __shared__ float sm[];
  float* sW   = sm;
  float* bufA = sm + 4352;
  float* bufB = sm + 13056;
  float* sP1  = sm + 21760;
  float4* sPos = (float4*)(sm + 22272);
  float* sB1  = sm + 22528;
  float* sB2  = sm + 22592;
  float4* sDir = (float4*)(sm + 22656);
  int*   sNb  = (int*)(sm + 23168);

  int dir = blockIdx.z, b = blockIdx.y;
  int n0 = blockIdx.x * 8;
  const float* p1 = dir ? g_f2b : g_f1a;
  const float* p2 = dir ? g_f1b : g_f2a;
  const float4* Qx = dir ? g_xyz[1] : g_xyz[0];
  const float4* Dx = dir ? g_xyz[0] : g_xyz[1];

  int t = threadIdx.x;

  // ---- load W1 transposed: sW[c*68+e] = Wm1[e*64+c] (coalesced read) ----
  #pragma unroll
  for (int i = 0; i < 16; i++) {
    int idx = t + i*256;            // idx = e*64 + c
    int e = idx >> 6, c = idx & 63;
    sW[c*68 + e] = Wm1[idx];
  }
  if (t < 64) {
    sPos[t] = make_float4(Wpos[t*3], Wpos[t*3+1], Wpos[t*3+2], bpos[t]);
    sB1[t] = b1[t];
    sB2[t] = b2[t];
  }
  #pragma unroll
  for (int i = 0; i < 2; i++) {
    int idx = t + i*256;            // 512 = 8q x 64d
    int q = idx >> 6, d = idx & 63;
    sP1[idx] = p1[(b*NN + n0 + q)*64 + d];
  }
  if (t < 128) {
    int q = t >> 4, k = t & 15;
    int nb = g_idx[((dir*BB + b)*NN + n0 + q)*16 + k];
    sNb[t] = nb;
    float4 dxv = Dx[b*NN + nb], qxv = Qx[b*NN + n0 + q];
    sDir[t] = make_float4(dxv.x - qxv.x, dxv.y - qxv.y, dxv.z - qxv.z, 0.f);
  }
  __syncthreads();

  // ---- stage 0: A[row][d] = leaky(g2 + p1 + pos), stored as bufA[d][row] --
  {
    int row = t & 127, half = t >> 7;
    int nb = sNb[row];
    int q = row >> 4;
    float4 dv = sDir[row];
    const float4* p2row = (const float4*)&p2[(b*NN + nb)*64] + half*8;
    const float* p1row = &sP1[q*64 + half*32];
    #pragma unroll
    for (int j = 0; j < 8; j++) {
      int d = half*32 + j*4;
      float4 g = p2row[j];
      float4 w0 = sPos[d+0], w1 = sPos[d+1], w2 = sPos[d+2], w3 = sPos[d+3];
      float v0 = g.x + p1row[j*4+0] + (dv.x*w0.x + dv.y*w0.y + dv.z*w0.z + w0.w);
      float v1 = g.y + p1row[j*4+1] + (dv.x*w1.x + dv.y*w1.y + dv.z*w1.z + w1.w);
      float v2 = g.z + p1row[j*4+2] + (dv.x*w2.x + dv.y*w2.y + dv.z*w2.z + w2.w);
      float v3 = g.w + p1row[j*4+3] + (dv.x*w3.x + dv.y*w3.y + dv.z*w3.z + w3.w);
      bufA[(d+0)*136 + row] = leaky(v0);
      bufA[(d+1)*136 + row] = leaky(v1);
      bufA[(d+2)*136 + row] = leaky(v2);
      bufA[(d+3)*136 + row] = leaky(v3);
    }
  }
  __syncthreads();

  int rq = t >> 4, tm = t & 15;
  int r0 = rq*8, e0 = tm*4;

  // ---- stage 1: bufB[e][row] = leaky(sum_c bufA[c][row]*W1[e][c] + b1) ----
  {
    float acc[8][4];
    #pragma unroll
    for (int i = 0; i < 8; i++)
      #pragma unroll
      for (int j = 0; j < 4; j++) acc[i][j] = 0.f;
    #pragma unroll 4
    for (int c = 0; c < 64; c++) {
      float4 wf = *(const float4*)&sW[c*68 + e0];
      float4 ra = *(const float4*)&bufA[c*136 + r0];
      float4 rb = *(const float4*)&bufA[c*136 + r0 + 4];
      float av[8] = {ra.x, ra.y, ra.z, ra.w, rb.x, rb.y, rb.z, rb.w};
      float wv[4] = {wf.x, wf.y, wf.z, wf.w};
      #pragma unroll
      for (int i = 0; i < 8; i++)
        #pragma unroll
        for (int j = 0; j < 4; j++) acc[i][j] += av[i]*wv[j];
    }
    #pragma unroll
    for (int j = 0; j < 4; j++) {
      float bb = sB1[e0 + j];
      float4 lo = make_float4(leaky(acc[0][j]+bb), leaky(acc[1][j]+bb),
                              leaky(acc[2][j]+bb), leaky(acc[3][j]+bb));
      float4 hi = make_float4(leaky(acc[4][j]+bb), leaky(acc[5][j]+bb),
                              leaky(acc[6][j]+bb), leaky(acc[7][j]+bb));
      *(float4*)&bufB[(e0+j)*136 + r0]     = lo;
      *(float4*)&bufB[(e0+j)*136 + r0 + 4] = hi;
    }
  }
  __syncthreads();

  // ---- reload sW with W2 transposed ----
  #pragma unroll
  for (int i = 0; i < 16; i++) {
    int idx = t + i*256;
    int e = idx >> 6, c = idx & 63;
    sW[c*68 + e] = Wm2[idx];
  }
  __syncthreads();

  // ---- stage 2: bufA[e][row] = leaky(sum_c bufB[c][row]*W2[e][c] + b2) ----
  {
    float acc[8][4];
    #pragma unroll
    for (int i = 0; i < 8; i++)
      #pragma unroll
      for (int j = 0; j < 4; j++) acc[i][j] = 0.f;
    #pragma unroll 4
    for (int c = 0; c < 64; c++) {
      float4 wf = *(const float4*)&sW[c*68 + e0];
      float4 ra = *(const float4*)&bufB[c*136 + r0];
      float4 rb = *(const float4*)&bufB[c*136 + r0 + 4];
      float av[8] = {ra.x, ra.y, ra.z, ra.w, rb.x, rb.y, rb.z, rb.w};
      float wv[4] = {wf.x, wf.y, wf.z, wf.w};
      #pragma unroll
      for (int i = 0; i < 8; i++)
        #pragma unroll
        for (int j = 0; j < 4; j++) acc[i][j] += av[i]*wv[j];
    }
    #pragma unroll
    for (int j = 0; j < 4; j++) {
      float bb = sB2[e0 + j];
      float4 lo = make_float4(leaky(acc[0][j]+bb), leaky(acc[1][j]+bb),
                              leaky(acc[2][j]+bb), leaky(acc[3][j]+bb));
      float4 hi = make_float4(leaky(acc[4][j]+bb), leaky(acc[5][j]+bb),
                              leaky(acc[6][j]+bb), leaky(acc[7][j]+bb));
      *(float4*)&bufA[(e0+j)*136 + r0]     = lo;
      *(float4*)&bufA[(e0+j)*136 + r0 + 4] = hi;
    }
  }
  __syncthreads();

  // ---- maxpool over k (16 contiguous rows per query) + store [e][n] ------
  #pragma unroll
  for (int i = 0; i < 2; i++) {
    int o = t + i*256;      // 512 outputs: q = o&7, e = o>>3
    int q = o & 7, e = o >> 3;
    const float4* r = (const float4*)&bufA[e*136 + q*16];
    float4 v0 = r[0], v1 = r[1], v2 = r[2], v3 = r[3];
    float m = fmaxf(fmaxf(fmaxf(v0.x, v0.y), fmaxf(v0.z, v0.w)),
                    fmaxf(fmaxf(v1.x, v1.y), fmaxf(v1.z, v1.w)));
    m = fmaxf(m, fmaxf(fmaxf(fmaxf(v2.x, v2.y), fmaxf(v2.z, v2.w)),
                       fmaxf(fmaxf(v3.x, v3.y), fmaxf(v3.z, v3.w))));
    out[dir*(BB*64*NN) + b*(64*NN) + e*NN + (n0 + q)] = m;
  }
}

// ---------------- launch ---------------------------------------------------
extern "C" void kernel_launch(void* const* d_in, const int* in_sizes, int n_in,
                              void* d_out, int out_size)
{
  const float* pc1   = (const float*)d_in[0];
  const float* pc2   = (const float*)d_in[1];
  const float* feat1 = (const float*)d_in[2];
  const float* feat2 = (const float*)d_in[3];
  const float* knn1  = (const float*)d_in[4];
  const float* knn2  = (const float*)d_in[5];
  const float* W11   = (const float*)d_in[6];
  const float* b11   = (const float*)d_in[7];
  const float* W22   = (const float*)d_in[8];
  const float* b22   = (const float*)d_in[9];
  const float* Wpos  = (const float*)d_in[10];
  const float* bpos  = (const float*)d_in[11];
  const float* Wm1   = (const float*)d_in[12];
  const float* bm1   = (const float*)d_in[13];
  const float* Wm2   = (const float*)d_in[14];
  const float* bm2   = (const float*)d_in[15];
  float* out = (float*)d_out;

  cudaFuncSetAttribute(k_knn_cos, cudaFuncAttributeMaxDynamicSharedMemorySize, 52224);
  cudaFuncSetAttribute(k_mlp, cudaFuncAttributeMaxDynamicSharedMemorySize, 93184);

  k_transform<<<dim3(64, 2, 4), 256>>>(feat1, feat2, W11, b11, W22, b22);
  k_normalize<<<dim3(64, 2, 2), 256>>>(knn1, knn2);
  k_xyz<<<dim3(16, 2, 2), 256>>>(pc1, pc2);
  k_knn_cos<<<dim3(64, 2, 2), 256, 52224>>>();
  k_euclid<<<dim3(64, 2, 2), 256>>>();
  k_mlp<<<dim3(512, 2, 2), 256, 93184>>>(Wpos, bpos, Wm1, bm1, Wm2, bm2, out);
}